// round 7
// baseline (speedup 1.0000x reference)
#include <cuda_runtime.h>
#include <math.h>

// Problem constants
#define Bz   32
#define Tt   512
#define CIN  64
#define NF   256
#define KW   9
#define GN   8
#define Hh   512
#define G4H  2048
#define NCLS 50

// ---------------------------------------------------------------------------
// Scratch (static device globals — no runtime allocation)
// ---------------------------------------------------------------------------
__device__ float g_feat0[(size_t)Tt * NF * Bz];        // conv out, (T,F,B)
__device__ float g_xg[(size_t)Tt * G4H * Bz];          // input projections, (T,4H,B)
__device__ float g_ht[(size_t)Tt * Hh * Bz];           // layer output, (T,H,B)
__device__ unsigned g_bar_ctr;
__device__ unsigned g_bar_phase;

__device__ __forceinline__ float fsig(float x) {
    return __fdividef(1.f, 1.f + __expf(-x));
}
__device__ __forceinline__ float ftanh(float x) {
    // tanh(x) = 1 - 2/(exp(2x)+1)
    return 1.f - __fdividef(2.f, __expf(2.f * x) + 1.f);
}

// ---------------------------------------------------------------------------
// Kernel 0: reset the grid-barrier counters (run before each layer kernel)
// ---------------------------------------------------------------------------
__global__ void bar_reset()
{
    g_bar_ctr = 0u;
    g_bar_phase = 0u;
}

// ---------------------------------------------------------------------------
// Kernel 1: Conv1d (pad 4) + GroupNorm + ReLU. grid = 256 (b*8+g), 512 thr.
// Output layout (T, F, B).
// ---------------------------------------------------------------------------
__global__ void __launch_bounds__(512)
conv_gn_relu(const float* __restrict__ x, const float* __restrict__ w,
             const float* __restrict__ gamma, const float* __restrict__ beta,
             float* __restrict__ out)
{
    extern __shared__ float sm[];
    float* xs = sm;                 // 16 * 520 floats
    float* ws = sm + 16 * 520;      // 16 * 9 * 32 floats, [(ci*9+k)*32 + c]
    __shared__ float rbuf[34];

    const int b   = blockIdx.x >> 3;
    const int grp = blockIdx.x & 7;
    const int tid = threadIdx.x;
    const int c   = tid & 31;
    const int tg  = tid >> 5;
    const int t0  = tg * 32;

    float acc[32];
#pragma unroll
    for (int i = 0; i < 32; i++) acc[i] = 0.f;

    for (int cc = 0; cc < 4; cc++) {
        for (int fi = tid; fi < 16 * 520; fi += 512) {
            int ci = fi / 520, tt = fi - ci * 520, t = tt - 4;
            float v = 0.f;
            if (t >= 0 && t < Tt)
                v = x[((size_t)b * CIN + cc * 16 + ci) * Tt + t];
            xs[fi] = v;
        }
        for (int fi = tid; fi < 16 * 9 * 32; fi += 512) {
            int c2 = fi / 144, rem = fi - c2 * 144, ci = rem / 9, k = rem - ci * 9;
            ws[(ci * 9 + k) * 32 + c2] =
                w[((size_t)(grp * 32 + c2)) * (CIN * KW) + (cc * 16 + ci) * KW + k];
        }
        __syncthreads();

        for (int ci = 0; ci < 16; ci++) {
            float xr[40];
            const float4* xsp = (const float4*)(xs + ci * 520 + t0);
#pragma unroll
            for (int i4 = 0; i4 < 10; i4++) {
                float4 v = xsp[i4];
                xr[i4 * 4 + 0] = v.x; xr[i4 * 4 + 1] = v.y;
                xr[i4 * 4 + 2] = v.z; xr[i4 * 4 + 3] = v.w;
            }
#pragma unroll
            for (int k = 0; k < 9; k++) {
                float wv = ws[(ci * 9 + k) * 32 + c];
#pragma unroll
                for (int t = 0; t < 32; t++)
                    acc[t] = fmaf(xr[t + k], wv, acc[t]);
            }
        }
        __syncthreads();
    }

    float s1 = 0.f, s2 = 0.f;
#pragma unroll
    for (int t = 0; t < 32; t++) { s1 += acc[t]; s2 = fmaf(acc[t], acc[t], s2); }
#pragma unroll
    for (int off = 16; off > 0; off >>= 1) {
        s1 += __shfl_xor_sync(0xffffffffu, s1, off);
        s2 += __shfl_xor_sync(0xffffffffu, s2, off);
    }
    int wid = tid >> 5;
    if ((tid & 31) == 0) { rbuf[wid] = s1; rbuf[16 + wid] = s2; }
    __syncthreads();
    if (tid < 32) {
        float a = (tid < 16) ? rbuf[tid] : 0.f;
        float bsum = (tid < 16) ? rbuf[16 + tid] : 0.f;
#pragma unroll
        for (int off = 8; off > 0; off >>= 1) {
            a += __shfl_xor_sync(0xffffffffu, a, off);
            bsum += __shfl_xor_sync(0xffffffffu, bsum, off);
        }
        if (tid == 0) {
            float mu = a * (1.f / 16384.f);
            float var = bsum * (1.f / 16384.f) - mu * mu;
            rbuf[32] = mu;
            rbuf[33] = rsqrtf(var + 1e-5f);
        }
    }
    __syncthreads();
    float mu = rbuf[32], rstd = rbuf[33];
    float ga = __ldg(gamma + grp * 32 + c);
    float be = __ldg(beta + grp * 32 + c);

#pragma unroll
    for (int t = 0; t < 32; t++) {
        float v = (acc[t] - mu) * rstd * ga + be;
        v = fmaxf(v, 0.f);
        out[((size_t)(t0 + t) * NF + grp * 32 + c) * 32 + b] = v;   // (T,F,B)
    }
}

// ---------------------------------------------------------------------------
// Kernel 2: input projection GEMM, A in (T,Kd,B) layout, out (T,4H,B).
// C[(t*4H + n)*32 + b] = sum_k A[(t*Kd + k)*32 + b] * W[n][k] + bias[n]
// Block tile: 4 t x 32 b (=128 rows) x 64 n. 256 threads, BK=16.
// ---------------------------------------------------------------------------
__global__ void __launch_bounds__(256)
gemm_xproj(const float* __restrict__ A, const float* __restrict__ W,
           const float* __restrict__ bias, float* __restrict__ C, int Kd)
{
    __shared__ float As[16 * 132];   // [k][r], padded
    __shared__ float Ws[16 * 68];    // [k][n], padded

    const int tid = threadIdx.x;
    const int n0 = blockIdx.x * 64;
    const int t0 = blockIdx.y * 4;
    const int tm = tid >> 4;         // 0..15 -> tile rows tm*8 .. +7
    const int tn = tid & 15;         // 0..15 -> cols n0 + tn*4 .. +3

    float acc[8][4];
#pragma unroll
    for (int i = 0; i < 8; i++)
#pragma unroll
        for (int j = 0; j < 4; j++) acc[i][j] = 0.f;

    for (int kt = 0; kt < Kd; kt += 16) {
        // A tile: 16 k x 4 t x 32 b, coalesced float4 over b
#pragma unroll
        for (int r2 = 0; r2 < 2; r2++) {
            int fi = tid + r2 * 256;          // 0..511
            int b4 = fi & 7;
            int tt = (fi >> 3) & 3;
            int k  = fi >> 5;                 // 0..15
            float4 v = *(const float4*)(A + ((size_t)(t0 + tt) * Kd + kt + k) * 32 + b4 * 4);
            int r = tt * 32 + b4 * 4;
            As[k * 132 + r + 0] = v.x;
            As[k * 132 + r + 1] = v.y;
            As[k * 132 + r + 2] = v.z;
            As[k * 132 + r + 3] = v.w;
        }
        {
            int n = tid >> 2, kq = tid & 3;
            float4 v = *(const float4*)(W + (size_t)(n0 + n) * Kd + kt + kq * 4);
            Ws[(kq * 4 + 0) * 68 + n] = v.x;
            Ws[(kq * 4 + 1) * 68 + n] = v.y;
            Ws[(kq * 4 + 2) * 68 + n] = v.z;
            Ws[(kq * 4 + 3) * 68 + n] = v.w;
        }
        __syncthreads();
#pragma unroll
        for (int k = 0; k < 16; k++) {
            float4 bv = *(float4*)&Ws[k * 68 + tn * 4];
            float4 a0 = *(float4*)&As[k * 132 + tm * 8];
            float4 a1 = *(float4*)&As[k * 132 + tm * 8 + 4];
            float av[8] = {a0.x, a0.y, a0.z, a0.w, a1.x, a1.y, a1.z, a1.w};
#pragma unroll
            for (int i = 0; i < 8; i++) {
                acc[i][0] = fmaf(av[i], bv.x, acc[i][0]);
                acc[i][1] = fmaf(av[i], bv.y, acc[i][1]);
                acc[i][2] = fmaf(av[i], bv.z, acc[i][2]);
                acc[i][3] = fmaf(av[i], bv.w, acc[i][3]);
            }
        }
        __syncthreads();
    }

    // Store: tile row r = tm*8+i -> tt = tm>>2, b = (tm&3)*8 + i.
    const int tt = tm >> 2;
    const int bb = (tm & 3) * 8;
    float4 bv = *(const float4*)(bias + n0 + tn * 4);
    const float bias_j[4] = {bv.x, bv.y, bv.z, bv.w};
#pragma unroll
    for (int j = 0; j < 4; j++) {
        float4 lo, hi;
        lo.x = acc[0][j] + bias_j[j]; lo.y = acc[1][j] + bias_j[j];
        lo.z = acc[2][j] + bias_j[j]; lo.w = acc[3][j] + bias_j[j];
        hi.x = acc[4][j] + bias_j[j]; hi.y = acc[5][j] + bias_j[j];
        hi.z = acc[6][j] + bias_j[j]; hi.w = acc[7][j] + bias_j[j];
        size_t base = ((size_t)(t0 + tt) * G4H + n0 + tn * 4 + j) * 32 + bb;
        *(float4*)(C + base)     = lo;
        *(float4*)(C + base + 4) = hi;
    }
}

// ---------------------------------------------------------------------------
// Kernel 3: persistent LSTM layer, 1024 threads/block (32 warps, 8/SMSP).
// grid = 128 blocks, 4 j per block. Thread = (b=lane, r = w>>3, ks = w&7):
// 8-way k-split per gate row; SMEM reduction; ks==0 eighth does the update.
// ---------------------------------------------------------------------------
__global__ void __launch_bounds__(1024)
lstm_layer(const float* __restrict__ xgT, const float* __restrict__ whh,
           float* __restrict__ ht)
{
    extern __shared__ float sm[];
    float* hs  = sm;            // 16384 floats: swizzled [k][b]
    float* wsm = sm + 16384;    // 8192 floats: 16 rows x 512, [(r*4+g)*512 + k]
    float* red = sm + 24576;    // 4096 floats: [(r*4+g)*8 + ks]*32 + b

    const int tid = threadIdx.x;
    const int b   = tid & 31;
    const int w   = tid >> 5;           // 0..31
    const int r   = w >> 3;             // 0..3 (local j)
    const int ks  = w & 7;              // k-eighth
    const int j0  = blockIdx.x * 4;
    const int j   = j0 + r;

    // stage 16 w_hh rows once — coalesced float4
    float4* wsm4 = (float4*)wsm;
    for (int fi = tid; fi < 2048; fi += 1024) {
        int lr = fi >> 7, kq = fi & 127;
        int g = lr & 3, rr = lr >> 2;
        int grow = g * Hh + j0 + rr;
        wsm4[lr * 128 + kq] = *(const float4*)(whh + (size_t)grow * Hh + kq * 4);
    }
    __syncthreads();

    const float4* w0 = (const float4*)(wsm + (r * 4 + 0) * 512) + ks * 16;
    const float4* w1 = (const float4*)(wsm + (r * 4 + 1) * 512) + ks * 16;
    const float4* w2 = (const float4*)(wsm + (r * 4 + 2) * 512) + ks * 16;
    const float4* w3 = (const float4*)(wsm + (r * 4 + 3) * 512) + ks * 16;

    float creg = 0.f;

    for (int t = 0; t < Tt; t++) {
        float gi, gf, gg, go;
        if (ks == 0) {
            const size_t xoff = ((size_t)t * G4H + j) * 32 + b;
            gi = __ldg(xgT + xoff);
            gf = __ldg(xgT + xoff + 512u * 32u);
            gg = __ldg(xgT + xoff + 1024u * 32u);
            go = __ldg(xgT + xoff + 1536u * 32u);
        }

        if (t > 0) {
            // stage h_{t-1} (32x512 from (T,H,B)), XOR bank swizzle
            const float4* hp = (const float4*)(ht + (size_t)(t - 1) * (Hh * Bz));
            float4* hs4 = (float4*)hs;
            for (int fi = tid; fi < 4096; fi += 1024) {
                int k = fi >> 3, b4i = fi & 7;
                float4 v = __ldcg(hp + fi);
                hs4[k * 8 + (b4i ^ (k & 7))] = v;
            }
            __syncthreads();

            float a0 = 0.f, a1 = 0.f, a2 = 0.f, a3 = 0.f;
#pragma unroll
            for (int k4 = 0; k4 < 16; k4++) {
                float4 v0 = w0[k4], v1 = w1[k4], v2 = w2[k4], v3 = w3[k4];
                int kb = (ks * 16 + k4) << 2;
                int shi = kb & 4;
                float h0 = hs[(kb + 0) * 32 + (b ^ ((shi | 0) << 2))];
                float h1 = hs[(kb + 1) * 32 + (b ^ ((shi | 1) << 2))];
                float h2 = hs[(kb + 2) * 32 + (b ^ ((shi | 2) << 2))];
                float h3 = hs[(kb + 3) * 32 + (b ^ ((shi | 3) << 2))];
                a0 = fmaf(h0, v0.x, a0); a0 = fmaf(h1, v0.y, a0);
                a0 = fmaf(h2, v0.z, a0); a0 = fmaf(h3, v0.w, a0);
                a1 = fmaf(h0, v1.x, a1); a1 = fmaf(h1, v1.y, a1);
                a1 = fmaf(h2, v1.z, a1); a1 = fmaf(h3, v1.w, a1);
                a2 = fmaf(h0, v2.x, a2); a2 = fmaf(h1, v2.y, a2);
                a2 = fmaf(h2, v2.z, a2); a2 = fmaf(h3, v2.w, a2);
                a3 = fmaf(h0, v3.x, a3); a3 = fmaf(h1, v3.y, a3);
                a3 = fmaf(h2, v3.z, a3); a3 = fmaf(h3, v3.w, a3);
            }
            red[((r * 4 + 0) * 8 + ks) * 32 + b] = a0;
            red[((r * 4 + 1) * 8 + ks) * 32 + b] = a1;
            red[((r * 4 + 2) * 8 + ks) * 32 + b] = a2;
            red[((r * 4 + 3) * 8 + ks) * 32 + b] = a3;
            __syncthreads();

            if (ks == 0) {
#pragma unroll
                for (int q = 0; q < 8; q++) {
                    gi += red[((r * 4 + 0) * 8 + q) * 32 + b];
                    gf += red[((r * 4 + 1) * 8 + q) * 32 + b];
                    gg += red[((r * 4 + 2) * 8 + q) * 32 + b];
                    go += red[((r * 4 + 3) * 8 + q) * 32 + b];
                }
            }
        }

        if (ks == 0) {
            float ii = fsig(gi);
            float ff = fsig(gf);
            float gt = ftanh(gg);
            float oo = fsig(go);
            creg = fmaf(ff, creg, ii * gt);
            float hn = oo * ftanh(creg);
            ht[(size_t)t * (Hh * Bz) + j * 32 + b] = hn;    // (T,H,B) coalesced
        }

        // ---- grid barrier: all ht[t] writes visible before anyone stages t+1
        __threadfence();
        __syncthreads();
        if (tid == 0) {
            unsigned target = (unsigned)(t + 1);
            unsigned old = atomicAdd(&g_bar_ctr, 1u);
            if (old == (unsigned)(gridDim.x - 1)) {
                atomicExch(&g_bar_ctr, 0u);
                __threadfence();
                atomicAdd(&g_bar_phase, 1u);
            } else {
                while (*(volatile unsigned*)&g_bar_phase < target)
                    __nanosleep(32);
            }
            __threadfence();
        }
        __syncthreads();
    }
}

// ---------------------------------------------------------------------------
// Kernel 4: mean-pool over T + linear head, reading (T,H,B). grid = 32 (b).
// ---------------------------------------------------------------------------
__global__ void __launch_bounds__(256)
head_pool(const float* __restrict__ h3, const float* __restrict__ hw,
          const float* __restrict__ hb, float* __restrict__ out)
{
    __shared__ float feat[512];
    const int b = blockIdx.x, tid = threadIdx.x;
    for (int j = tid; j < Hh; j += 256) {
        float s = 0.f;
        for (int t = 0; t < Tt; t++)
            s += h3[((size_t)t * Hh + j) * 32 + b];
        feat[j] = s * (1.f / (float)Tt);
    }
    __syncthreads();
    for (int n = tid; n < NCLS; n += 256) {
        float s = __ldg(hb + n);
        for (int jj = 0; jj < Hh; jj++)
            s = fmaf(feat[jj], __ldg(hw + (size_t)n * Hh + jj), s);
        out[b * NCLS + n] = s;
    }
}

// ---------------------------------------------------------------------------
// Host launcher
// ---------------------------------------------------------------------------
extern "C" void kernel_launch(void* const* d_in, const int* in_sizes, int n_in,
                              void* d_out, int out_size)
{
    (void)out_size;
    const float* x     = (const float*)d_in[0];
    const float* convw = (const float*)d_in[1];
    const float* gam   = (const float*)d_in[2];
    const float* bet   = (const float*)d_in[3];
    const float *hw, *hb, *wih[3], *whh[3], *bvec[3];

    if (n_in >= 15 && in_sizes[4] == NCLS * Hh) {
        hw = (const float*)d_in[4];
        hb = (const float*)d_in[5];
        for (int l = 0; l < 3; l++) {
            wih[l]  = (const float*)d_in[6 + 3 * l];
            whh[l]  = (const float*)d_in[7 + 3 * l];
            bvec[l] = (const float*)d_in[8 + 3 * l];
        }
    } else {
        for (int l = 0; l < 3; l++) {
            wih[l]  = (const float*)d_in[4 + 3 * l];
            whh[l]  = (const float*)d_in[5 + 3 * l];
            bvec[l] = (const float*)d_in[6 + 3 * l];
        }
        hw = (const float*)d_in[13];
        hb = (const float*)d_in[14];
    }

    float *feat0, *xgp, *htp;
    cudaGetSymbolAddress((void**)&feat0, g_feat0);
    cudaGetSymbolAddress((void**)&xgp,   g_xg);
    cudaGetSymbolAddress((void**)&htp,   g_ht);

    const int conv_smem  = (16 * 520 + 16 * 9 * 32) * 4;   // 51712 B
    const int layer_smem = (16384 + 8192 + 4096) * 4;      // 114688 B
    cudaFuncSetAttribute(conv_gn_relu, cudaFuncAttributeMaxDynamicSharedMemorySize, conv_smem);
    cudaFuncSetAttribute(lstm_layer,   cudaFuncAttributeMaxDynamicSharedMemorySize, layer_smem);

    conv_gn_relu<<<Bz * GN, 512, conv_smem>>>(x, convw, gam, bet, feat0);

    for (int l = 0; l < 3; l++) {
        const float* Ain = (l == 0) ? feat0 : htp;
        const int Kd = (l == 0) ? NF : Hh;
        gemm_xproj<<<dim3(G4H / 64, Tt / 4), 256>>>(Ain, wih[l], bvec[l], xgp, Kd);
        bar_reset<<<1, 1>>>();
        lstm_layer<<<128, 1024, layer_smem>>>(xgp, whh[l], htp);
    }

    head_pool<<<Bz, 256>>>(htp, hw, hb, (float*)d_out);
}

// round 15
// speedup vs baseline: 1.0461x; 1.0461x over previous
#include <cuda_runtime.h>
#include <math.h>

// Problem constants
#define Bz   32
#define Tt   512
#define CIN  64
#define NF   256
#define KW   9
#define GN   8
#define Hh   512
#define G4H  2048
#define NCLS 50

// Packed fp32x2 FMA (Blackwell FFMA2) — only reachable via PTX.
#define FFMA2(acc, a_, b_) \
    asm("fma.rn.f32x2 %0, %1, %2, %0;" : "+l"(acc) : "l"(a_), "l"(b_))

// ---------------------------------------------------------------------------
// Scratch (static device globals — no runtime allocation)
// ---------------------------------------------------------------------------
__device__ float g_feat0[(size_t)Tt * Bz * NF];        // conv out, (T,B,F)
__device__ float g_xg[(size_t)Tt * G4H * Bz];          // input projections, (T,4H,B)
__device__ float g_ht[(size_t)Tt * Bz * Hh];           // layer output, (T,B,H)
__device__ unsigned g_bar_ctr;
__device__ unsigned g_bar_phase;

__device__ __forceinline__ float fsig(float x) {
    return __fdividef(1.f, 1.f + __expf(-x));
}
__device__ __forceinline__ float ftanh(float x) {
    return 1.f - __fdividef(2.f, __expf(2.f * x) + 1.f);
}

// ---------------------------------------------------------------------------
// Kernel 0: reset the grid-barrier counters (run before each layer kernel)
// ---------------------------------------------------------------------------
__global__ void bar_reset()
{
    g_bar_ctr = 0u;
    g_bar_phase = 0u;
}

// ---------------------------------------------------------------------------
// Kernel 1: Conv1d (pad 4) + GroupNorm + ReLU. grid = 256 (b*8+g), 512 thr.
// Output layout (T, B, F)  — store is coalesced over c.
// ---------------------------------------------------------------------------
__global__ void __launch_bounds__(512)
conv_gn_relu(const float* __restrict__ x, const float* __restrict__ w,
             const float* __restrict__ gamma, const float* __restrict__ beta,
             float* __restrict__ out)
{
    extern __shared__ float sm[];
    float* xs = sm;                 // 16 * 520 floats
    float* ws = sm + 16 * 520;      // 16 * 9 * 32 floats, [(ci*9+k)*32 + c]
    __shared__ float rbuf[34];

    const int b   = blockIdx.x >> 3;
    const int grp = blockIdx.x & 7;
    const int tid = threadIdx.x;
    const int c   = tid & 31;
    const int tg  = tid >> 5;
    const int t0  = tg * 32;

    float acc[32];
#pragma unroll
    for (int i = 0; i < 32; i++) acc[i] = 0.f;

    for (int cc = 0; cc < 4; cc++) {
        for (int fi = tid; fi < 16 * 520; fi += 512) {
            int ci = fi / 520, tt = fi - ci * 520, t = tt - 4;
            float v = 0.f;
            if (t >= 0 && t < Tt)
                v = x[((size_t)b * CIN + cc * 16 + ci) * Tt + t];
            xs[fi] = v;
        }
        for (int fi = tid; fi < 16 * 9 * 32; fi += 512) {
            int c2 = fi / 144, rem = fi - c2 * 144, ci = rem / 9, k = rem - ci * 9;
            ws[(ci * 9 + k) * 32 + c2] =
                w[((size_t)(grp * 32 + c2)) * (CIN * KW) + (cc * 16 + ci) * KW + k];
        }
        __syncthreads();

        for (int ci = 0; ci < 16; ci++) {
            float xr[40];
            const float4* xsp = (const float4*)(xs + ci * 520 + t0);
#pragma unroll
            for (int i4 = 0; i4 < 10; i4++) {
                float4 v = xsp[i4];
                xr[i4 * 4 + 0] = v.x; xr[i4 * 4 + 1] = v.y;
                xr[i4 * 4 + 2] = v.z; xr[i4 * 4 + 3] = v.w;
            }
#pragma unroll
            for (int k = 0; k < 9; k++) {
                float wv = ws[(ci * 9 + k) * 32 + c];
#pragma unroll
                for (int t = 0; t < 32; t++)
                    acc[t] = fmaf(xr[t + k], wv, acc[t]);
            }
        }
        __syncthreads();
    }

    float s1 = 0.f, s2 = 0.f;
#pragma unroll
    for (int t = 0; t < 32; t++) { s1 += acc[t]; s2 = fmaf(acc[t], acc[t], s2); }
#pragma unroll
    for (int off = 16; off > 0; off >>= 1) {
        s1 += __shfl_xor_sync(0xffffffffu, s1, off);
        s2 += __shfl_xor_sync(0xffffffffu, s2, off);
    }
    int wid = tid >> 5;
    if ((tid & 31) == 0) { rbuf[wid] = s1; rbuf[16 + wid] = s2; }
    __syncthreads();
    if (tid < 32) {
        float a = (tid < 16) ? rbuf[tid] : 0.f;
        float bsum = (tid < 16) ? rbuf[16 + tid] : 0.f;
#pragma unroll
        for (int off = 8; off > 0; off >>= 1) {
            a += __shfl_xor_sync(0xffffffffu, a, off);
            bsum += __shfl_xor_sync(0xffffffffu, bsum, off);
        }
        if (tid == 0) {
            float mu = a * (1.f / 16384.f);
            float var = bsum * (1.f / 16384.f) - mu * mu;
            rbuf[32] = mu;
            rbuf[33] = rsqrtf(var + 1e-5f);
        }
    }
    __syncthreads();
    float mu = rbuf[32], rstd = rbuf[33];
    float ga = __ldg(gamma + grp * 32 + c);
    float be = __ldg(beta + grp * 32 + c);

#pragma unroll
    for (int t = 0; t < 32; t++) {
        float v = (acc[t] - mu) * rstd * ga + be;
        v = fmaxf(v, 0.f);
        out[((size_t)(t0 + t) * Bz + b) * NF + grp * 32 + c] = v;   // (T,B,F)
    }
}

// ---------------------------------------------------------------------------
// Kernel 2: input projection GEMM, A row-major (T*B, Kd), out (T,4H,B).
// C[(t*4H + n)*32 + b] = sum_k A[(t*32+b)*Kd + k] * W[n][k] + bias[n]
// Block tile: 128 rows (4 t x 32 b) x 64 n. 256 threads, BK=16.
// ---------------------------------------------------------------------------
__global__ void __launch_bounds__(256)
gemm_xproj(const float* __restrict__ A, const float* __restrict__ W,
           const float* __restrict__ bias, float* __restrict__ C, int Kd)
{
    __shared__ float As[16 * 132];   // [k][r], padded
    __shared__ float Ws[16 * 68];    // [k][n], padded

    const int tid = threadIdx.x;
    const int n0 = blockIdx.x * 64;
    const int t0 = blockIdx.y * 4;
    const int tm = tid >> 4;         // 0..15 -> tile rows tm*8 .. +7
    const int tn = tid & 15;         // 0..15 -> cols n0 + tn*4 .. +3

    float acc[8][4];
#pragma unroll
    for (int i = 0; i < 8; i++)
#pragma unroll
        for (int j = 0; j < 4; j++) acc[i][j] = 0.f;

    for (int kt = 0; kt < Kd; kt += 16) {
        // A tile: rows r = tt*32+bb are consecutive rows of A
#pragma unroll
        for (int r2 = 0; r2 < 2; r2++) {
            int fi = tid + r2 * 256;
            int r = fi >> 2, kq = fi & 3;
            float4 v = *(const float4*)(A + (size_t)(t0 * 32 + r) * Kd + kt + kq * 4);
            As[(kq * 4 + 0) * 132 + r] = v.x;
            As[(kq * 4 + 1) * 132 + r] = v.y;
            As[(kq * 4 + 2) * 132 + r] = v.z;
            As[(kq * 4 + 3) * 132 + r] = v.w;
        }
        {
            int n = tid >> 2, kq = tid & 3;
            float4 v = *(const float4*)(W + (size_t)(n0 + n) * Kd + kt + kq * 4);
            Ws[(kq * 4 + 0) * 68 + n] = v.x;
            Ws[(kq * 4 + 1) * 68 + n] = v.y;
            Ws[(kq * 4 + 2) * 68 + n] = v.z;
            Ws[(kq * 4 + 3) * 68 + n] = v.w;
        }
        __syncthreads();
#pragma unroll
        for (int k = 0; k < 16; k++) {
            float4 bv = *(float4*)&Ws[k * 68 + tn * 4];
            float4 a0 = *(float4*)&As[k * 132 + tm * 8];
            float4 a1 = *(float4*)&As[k * 132 + tm * 8 + 4];
            float av[8] = {a0.x, a0.y, a0.z, a0.w, a1.x, a1.y, a1.z, a1.w};
#pragma unroll
            for (int i = 0; i < 8; i++) {
                acc[i][0] = fmaf(av[i], bv.x, acc[i][0]);
                acc[i][1] = fmaf(av[i], bv.y, acc[i][1]);
                acc[i][2] = fmaf(av[i], bv.z, acc[i][2]);
                acc[i][3] = fmaf(av[i], bv.w, acc[i][3]);
            }
        }
        __syncthreads();
    }

    // Store to (T,4H,B): tile row r = tm*8+i -> tt = tm>>2, b = (tm&3)*8 + i.
    const int tt = tm >> 2;
    const int bb = (tm & 3) * 8;
    float4 bv = *(const float4*)(bias + n0 + tn * 4);
    const float bias_j[4] = {bv.x, bv.y, bv.z, bv.w};
#pragma unroll
    for (int j = 0; j < 4; j++) {
        float4 lo, hi;
        lo.x = acc[0][j] + bias_j[j]; lo.y = acc[1][j] + bias_j[j];
        lo.z = acc[2][j] + bias_j[j]; lo.w = acc[3][j] + bias_j[j];
        hi.x = acc[4][j] + bias_j[j]; hi.y = acc[5][j] + bias_j[j];
        hi.z = acc[6][j] + bias_j[j]; hi.w = acc[7][j] + bias_j[j];
        size_t base = ((size_t)(t0 + tt) * G4H + n0 + tn * 4 + j) * 32 + bb;
        *(float4*)(C + base)     = lo;
        *(float4*)(C + base + 4) = hi;
    }
}

// ---------------------------------------------------------------------------
// Kernel 3: persistent LSTM layer, 512 threads/block, packed f32x2 dot.
// grid = 128 blocks, 4 j per block. Thread = (b=lane, r = w>>2, ks = w&3):
// 4-way k-split (kslice=128); h tile transposed hs[b][k] (pad 516);
// global h state in (T,B,H).
// ---------------------------------------------------------------------------
#define HSP 516   // padded row stride of hs (floats)

__global__ void __launch_bounds__(512)
lstm_layer(const float* __restrict__ xgT, const float* __restrict__ whh,
           float* __restrict__ ht)
{
    extern __shared__ float sm[];
    float* hs  = sm;               // 32 * 516 floats: hs[b][k]
    float* wsm = sm + 32 * HSP;    // 8192 floats: 16 rows x 512, [(r*4+g)*512 + k]
    float* red = wsm + 8192;       // 2048 floats: [(r*4+g)*4 + ks]*32 + b

    const int tid = threadIdx.x;
    const int b   = tid & 31;
    const int w   = tid >> 5;           // 0..15
    const int r   = w >> 2;             // 0..3 (local j)
    const int ks  = w & 3;              // k-quarter (128 k each)
    const int j0  = blockIdx.x * 4;
    const int j   = j0 + r;

    // stage 16 w_hh rows once — coalesced float4
    float4* wsm4 = (float4*)wsm;
    for (int fi = tid; fi < 2048; fi += 512) {
        int lr = fi >> 7, kq = fi & 127;
        int g = lr & 3, rr = lr >> 2;
        int grow = g * Hh + j0 + rr;
        wsm4[lr * 128 + kq] = *(const float4*)(whh + (size_t)grow * Hh + kq * 4);
    }
    __syncthreads();

    const ulonglong2* w0 = (const ulonglong2*)(wsm + (r * 4 + 0) * 512 + ks * 128);
    const ulonglong2* w1 = (const ulonglong2*)(wsm + (r * 4 + 1) * 512 + ks * 128);
    const ulonglong2* w2 = (const ulonglong2*)(wsm + (r * 4 + 2) * 512 + ks * 128);
    const ulonglong2* w3 = (const ulonglong2*)(wsm + (r * 4 + 3) * 512 + ks * 128);
    const ulonglong2* hv = (const ulonglong2*)(hs + b * HSP + ks * 128);

    float creg = 0.f;

    for (int t = 0; t < Tt; t++) {
        float gi, gf, gg, go;
        if (ks == 0) {
            const size_t xoff = ((size_t)t * G4H + j) * 32 + b;
            gi = __ldg(xgT + xoff);
            gf = __ldg(xgT + xoff + 512u * 32u);
            gg = __ldg(xgT + xoff + 1024u * 32u);
            go = __ldg(xgT + xoff + 1536u * 32u);
        }

        if (t > 0) {
            // stage h_{t-1} from (T,B,H) into transposed hs[b][k]
            const float4* hp = (const float4*)(ht + (size_t)(t - 1) * (Hh * Bz));
            for (int fi = tid; fi < 4096; fi += 512) {
                int bb = fi >> 7, kq = fi & 127;
                float4 v = __ldcg(hp + bb * 128 + kq);
                *(float4*)(hs + bb * HSP + kq * 4) = v;
            }
            __syncthreads();

            unsigned long long acc0 = 0ull, acc1 = 0ull, acc2 = 0ull, acc3 = 0ull;
#pragma unroll 8
            for (int k4 = 0; k4 < 32; k4++) {
                ulonglong2 hq = hv[k4];
                ulonglong2 q0 = w0[k4];
                ulonglong2 q1 = w1[k4];
                ulonglong2 q2 = w2[k4];
                ulonglong2 q3 = w3[k4];
                FFMA2(acc0, hq.x, q0.x); FFMA2(acc0, hq.y, q0.y);
                FFMA2(acc1, hq.x, q1.x); FFMA2(acc1, hq.y, q1.y);
                FFMA2(acc2, hq.x, q2.x); FFMA2(acc2, hq.y, q2.y);
                FFMA2(acc3, hq.x, q3.x); FFMA2(acc3, hq.y, q3.y);
            }
            float l0, h0, l1, h1, l2, h2, l3, h3;
            asm("mov.b64 {%0, %1}, %2;" : "=f"(l0), "=f"(h0) : "l"(acc0));
            asm("mov.b64 {%0, %1}, %2;" : "=f"(l1), "=f"(h1) : "l"(acc1));
            asm("mov.b64 {%0, %1}, %2;" : "=f"(l2), "=f"(h2) : "l"(acc2));
            asm("mov.b64 {%0, %1}, %2;" : "=f"(l3), "=f"(h3) : "l"(acc3));

            red[((r * 4 + 0) * 4 + ks) * 32 + b] = l0 + h0;
            red[((r * 4 + 1) * 4 + ks) * 32 + b] = l1 + h1;
            red[((r * 4 + 2) * 4 + ks) * 32 + b] = l2 + h2;
            red[((r * 4 + 3) * 4 + ks) * 32 + b] = l3 + h3;
            __syncthreads();

            if (ks == 0) {
#pragma unroll
                for (int q = 0; q < 4; q++) {
                    gi += red[((r * 4 + 0) * 4 + q) * 32 + b];
                    gf += red[((r * 4 + 1) * 4 + q) * 32 + b];
                    gg += red[((r * 4 + 2) * 4 + q) * 32 + b];
                    go += red[((r * 4 + 3) * 4 + q) * 32 + b];
                }
            }
        }

        if (ks == 0) {
            float ii = fsig(gi);
            float ff = fsig(gf);
            float gt = ftanh(gg);
            float oo = fsig(go);
            creg = fmaf(ff, creg, ii * gt);
            float hn = oo * ftanh(creg);
            ht[(size_t)t * (Hh * Bz) + b * Hh + j] = hn;    // (T,B,H)
        }

        // ---- grid barrier: all ht[t] writes visible before anyone stages t+1
        __threadfence();
        __syncthreads();
        if (tid == 0) {
            unsigned target = (unsigned)(t + 1);
            unsigned old = atomicAdd(&g_bar_ctr, 1u);
            if (old == (unsigned)(gridDim.x - 1)) {
                atomicExch(&g_bar_ctr, 0u);
                __threadfence();
                atomicAdd(&g_bar_phase, 1u);
            } else {
                while (*(volatile unsigned*)&g_bar_phase < target)
                    __nanosleep(32);
            }
            __threadfence();
        }
        __syncthreads();
    }
}

// ---------------------------------------------------------------------------
// Kernel 4: mean-pool over T + linear head, reading (T,B,H). grid = 32 (b).
// ---------------------------------------------------------------------------
__global__ void __launch_bounds__(256)
head_pool(const float* __restrict__ h3, const float* __restrict__ hw,
          const float* __restrict__ hb, float* __restrict__ out)
{
    __shared__ float feat[512];
    const int b = blockIdx.x, tid = threadIdx.x;
    for (int j = tid; j < Hh; j += 256) {
        float s = 0.f;
        for (int t = 0; t < Tt; t++)
            s += h3[((size_t)t * Bz + b) * Hh + j];
        feat[j] = s * (1.f / (float)Tt);
    }
    __syncthreads();
    for (int n = tid; n < NCLS; n += 256) {
        float s = __ldg(hb + n);
        for (int jj = 0; jj < Hh; jj++)
            s = fmaf(feat[jj], __ldg(hw + (size_t)n * Hh + jj), s);
        out[b * NCLS + n] = s;
    }
}

// ---------------------------------------------------------------------------
// Host launcher
// ---------------------------------------------------------------------------
extern "C" void kernel_launch(void* const* d_in, const int* in_sizes, int n_in,
                              void* d_out, int out_size)
{
    (void)out_size;
    const float* x     = (const float*)d_in[0];
    const float* convw = (const float*)d_in[1];
    const float* gam   = (const float*)d_in[2];
    const float* bet   = (const float*)d_in[3];
    const float *hw, *hb, *wih[3], *whh[3], *bvec[3];

    if (n_in >= 15 && in_sizes[4] == NCLS * Hh) {
        hw = (const float*)d_in[4];
        hb = (const float*)d_in[5];
        for (int l = 0; l < 3; l++) {
            wih[l]  = (const float*)d_in[6 + 3 * l];
            whh[l]  = (const float*)d_in[7 + 3 * l];
            bvec[l] = (const float*)d_in[8 + 3 * l];
        }
    } else {
        for (int l = 0; l < 3; l++) {
            wih[l]  = (const float*)d_in[4 + 3 * l];
            whh[l]  = (const float*)d_in[5 + 3 * l];
            bvec[l] = (const float*)d_in[6 + 3 * l];
        }
        hw = (const float*)d_in[13];
        hb = (const float*)d_in[14];
    }

    float *feat0, *xgp, *htp;
    cudaGetSymbolAddress((void**)&feat0, g_feat0);
    cudaGetSymbolAddress((void**)&xgp,   g_xg);
    cudaGetSymbolAddress((void**)&htp,   g_ht);

    const int conv_smem  = (16 * 520 + 16 * 9 * 32) * 4;          // 51712 B
    const int layer_smem = (32 * HSP + 8192 + 2048) * 4;          // 107008 B
    cudaFuncSetAttribute(conv_gn_relu, cudaFuncAttributeMaxDynamicSharedMemorySize, conv_smem);
    cudaFuncSetAttribute(lstm_layer,   cudaFuncAttributeMaxDynamicSharedMemorySize, layer_smem);

    conv_gn_relu<<<Bz * GN, 512, conv_smem>>>(x, convw, gam, bet, feat0);

    for (int l = 0; l < 3; l++) {
        const float* Ain = (l == 0) ? feat0 : htp;
        const int Kd = (l == 0) ? NF : Hh;
        gemm_xproj<<<dim3(G4H / 64, Tt / 4), 256>>>(Ain, wih[l], bvec[l], xgp, Kd);
        bar_reset<<<1, 1>>>();
        lstm_layer<<<128, 512, layer_smem>>>(xgp, whh[l], htp);
    }

    head_pool<<<Bz, 256>>>(htp, hw, hb, (float*)d_out);
}

// round 16
// speedup vs baseline: 1.1697x; 1.1182x over previous
#include <cuda_runtime.h>
#include <math.h>

// Problem constants
#define Bz   32
#define Tt   512
#define CIN  64
#define NF   256
#define KW   9
#define GN   8
#define Hh   512
#define G4H  2048
#define NCLS 50

// Packed fp32x2 FMA (Blackwell FFMA2) — only reachable via PTX.
#define FFMA2(acc, a_, b_) \
    asm("fma.rn.f32x2 %0, %1, %2, %0;" : "+l"(acc) : "l"(a_), "l"(b_))

// ---------------------------------------------------------------------------
// Scratch (static device globals — no runtime allocation)
// ---------------------------------------------------------------------------
__device__ float g_feat0[(size_t)Tt * Bz * NF];        // conv out, (T,B,F)
__device__ float g_xg[(size_t)Tt * G4H * Bz];          // input projections, (T,4H,B)
__device__ float g_ht[(size_t)Tt * Bz * Hh];           // layer output, (T,B,H)
__device__ unsigned g_bar_ctr;                         // monotonic arrival counter

__device__ __forceinline__ float fsig(float x) {
    return __fdividef(1.f, 1.f + __expf(-x));
}
__device__ __forceinline__ float ftanh(float x) {
    return 1.f - __fdividef(2.f, __expf(2.f * x) + 1.f);
}

// ---------------------------------------------------------------------------
// Kernel 0: reset the barrier counter (run before each layer kernel)
// ---------------------------------------------------------------------------
__global__ void bar_reset()
{
    g_bar_ctr = 0u;
}

// ---------------------------------------------------------------------------
// Kernel 1: Conv1d (pad 4) + GroupNorm + ReLU. grid = 256 (b*8+g), 512 thr.
// Output layout (T, B, F)  — store is coalesced over c.
// ---------------------------------------------------------------------------
__global__ void __launch_bounds__(512)
conv_gn_relu(const float* __restrict__ x, const float* __restrict__ w,
             const float* __restrict__ gamma, const float* __restrict__ beta,
             float* __restrict__ out)
{
    extern __shared__ float sm[];
    float* xs = sm;                 // 16 * 520 floats
    float* ws = sm + 16 * 520;      // 16 * 9 * 32 floats, [(ci*9+k)*32 + c]
    __shared__ float rbuf[34];

    const int b   = blockIdx.x >> 3;
    const int grp = blockIdx.x & 7;
    const int tid = threadIdx.x;
    const int c   = tid & 31;
    const int tg  = tid >> 5;
    const int t0  = tg * 32;

    float acc[32];
#pragma unroll
    for (int i = 0; i < 32; i++) acc[i] = 0.f;

    for (int cc = 0; cc < 4; cc++) {
        for (int fi = tid; fi < 16 * 520; fi += 512) {
            int ci = fi / 520, tt = fi - ci * 520, t = tt - 4;
            float v = 0.f;
            if (t >= 0 && t < Tt)
                v = x[((size_t)b * CIN + cc * 16 + ci) * Tt + t];
            xs[fi] = v;
        }
        for (int fi = tid; fi < 16 * 9 * 32; fi += 512) {
            int c2 = fi / 144, rem = fi - c2 * 144, ci = rem / 9, k = rem - ci * 9;
            ws[(ci * 9 + k) * 32 + c2] =
                w[((size_t)(grp * 32 + c2)) * (CIN * KW) + (cc * 16 + ci) * KW + k];
        }
        __syncthreads();

        for (int ci = 0; ci < 16; ci++) {
            float xr[40];
            const float4* xsp = (const float4*)(xs + ci * 520 + t0);
#pragma unroll
            for (int i4 = 0; i4 < 10; i4++) {
                float4 v = xsp[i4];
                xr[i4 * 4 + 0] = v.x; xr[i4 * 4 + 1] = v.y;
                xr[i4 * 4 + 2] = v.z; xr[i4 * 4 + 3] = v.w;
            }
#pragma unroll
            for (int k = 0; k < 9; k++) {
                float wv = ws[(ci * 9 + k) * 32 + c];
#pragma unroll
                for (int t = 0; t < 32; t++)
                    acc[t] = fmaf(xr[t + k], wv, acc[t]);
            }
        }
        __syncthreads();
    }

    float s1 = 0.f, s2 = 0.f;
#pragma unroll
    for (int t = 0; t < 32; t++) { s1 += acc[t]; s2 = fmaf(acc[t], acc[t], s2); }
#pragma unroll
    for (int off = 16; off > 0; off >>= 1) {
        s1 += __shfl_xor_sync(0xffffffffu, s1, off);
        s2 += __shfl_xor_sync(0xffffffffu, s2, off);
    }
    int wid = tid >> 5;
    if ((tid & 31) == 0) { rbuf[wid] = s1; rbuf[16 + wid] = s2; }
    __syncthreads();
    if (tid < 32) {
        float a = (tid < 16) ? rbuf[tid] : 0.f;
        float bsum = (tid < 16) ? rbuf[16 + tid] : 0.f;
#pragma unroll
        for (int off = 8; off > 0; off >>= 1) {
            a += __shfl_xor_sync(0xffffffffu, a, off);
            bsum += __shfl_xor_sync(0xffffffffu, bsum, off);
        }
        if (tid == 0) {
            float mu = a * (1.f / 16384.f);
            float var = bsum * (1.f / 16384.f) - mu * mu;
            rbuf[32] = mu;
            rbuf[33] = rsqrtf(var + 1e-5f);
        }
    }
    __syncthreads();
    float mu = rbuf[32], rstd = rbuf[33];
    float ga = __ldg(gamma + grp * 32 + c);
    float be = __ldg(beta + grp * 32 + c);

#pragma unroll
    for (int t = 0; t < 32; t++) {
        float v = (acc[t] - mu) * rstd * ga + be;
        v = fmaxf(v, 0.f);
        out[((size_t)(t0 + t) * Bz + b) * NF + grp * 32 + c] = v;   // (T,B,F)
    }
}

// ---------------------------------------------------------------------------
// Kernel 2: input projection GEMM, A row-major (T*B, Kd), out (T,4H,B).
// C[(t*4H + n)*32 + b] = sum_k A[(t*32+b)*Kd + k] * W[n][k] + bias[n]
// Block tile: 128 rows (4 t x 32 b) x 64 n. 256 threads, BK=16.
// ---------------------------------------------------------------------------
__global__ void __launch_bounds__(256)
gemm_xproj(const float* __restrict__ A, const float* __restrict__ W,
           const float* __restrict__ bias, float* __restrict__ C, int Kd)
{
    __shared__ float As[16 * 132];   // [k][r], padded
    __shared__ float Ws[16 * 68];    // [k][n], padded

    const int tid = threadIdx.x;
    const int n0 = blockIdx.x * 64;
    const int t0 = blockIdx.y * 4;
    const int tm = tid >> 4;         // 0..15 -> tile rows tm*8 .. +7
    const int tn = tid & 15;         // 0..15 -> cols n0 + tn*4 .. +3

    float acc[8][4];
#pragma unroll
    for (int i = 0; i < 8; i++)
#pragma unroll
        for (int j = 0; j < 4; j++) acc[i][j] = 0.f;

    for (int kt = 0; kt < Kd; kt += 16) {
        // A tile: rows r = tt*32+bb are consecutive rows of A
#pragma unroll
        for (int r2 = 0; r2 < 2; r2++) {
            int fi = tid + r2 * 256;
            int r = fi >> 2, kq = fi & 3;
            float4 v = *(const float4*)(A + (size_t)(t0 * 32 + r) * Kd + kt + kq * 4);
            As[(kq * 4 + 0) * 132 + r] = v.x;
            As[(kq * 4 + 1) * 132 + r] = v.y;
            As[(kq * 4 + 2) * 132 + r] = v.z;
            As[(kq * 4 + 3) * 132 + r] = v.w;
        }
        {
            int n = tid >> 2, kq = tid & 3;
            float4 v = *(const float4*)(W + (size_t)(n0 + n) * Kd + kt + kq * 4);
            Ws[(kq * 4 + 0) * 68 + n] = v.x;
            Ws[(kq * 4 + 1) * 68 + n] = v.y;
            Ws[(kq * 4 + 2) * 68 + n] = v.z;
            Ws[(kq * 4 + 3) * 68 + n] = v.w;
        }
        __syncthreads();
#pragma unroll
        for (int k = 0; k < 16; k++) {
            float4 bv = *(float4*)&Ws[k * 68 + tn * 4];
            float4 a0 = *(float4*)&As[k * 132 + tm * 8];
            float4 a1 = *(float4*)&As[k * 132 + tm * 8 + 4];
            float av[8] = {a0.x, a0.y, a0.z, a0.w, a1.x, a1.y, a1.z, a1.w};
#pragma unroll
            for (int i = 0; i < 8; i++) {
                acc[i][0] = fmaf(av[i], bv.x, acc[i][0]);
                acc[i][1] = fmaf(av[i], bv.y, acc[i][1]);
                acc[i][2] = fmaf(av[i], bv.z, acc[i][2]);
                acc[i][3] = fmaf(av[i], bv.w, acc[i][3]);
            }
        }
        __syncthreads();
    }

    // Store to (T,4H,B): tile row r = tm*8+i -> tt = tm>>2, b = (tm&3)*8 + i.
    const int tt = tm >> 2;
    const int bb = (tm & 3) * 8;
    float4 bv = *(const float4*)(bias + n0 + tn * 4);
    const float bias_j[4] = {bv.x, bv.y, bv.z, bv.w};
#pragma unroll
    for (int j = 0; j < 4; j++) {
        float4 lo, hi;
        lo.x = acc[0][j] + bias_j[j]; lo.y = acc[1][j] + bias_j[j];
        lo.z = acc[2][j] + bias_j[j]; lo.w = acc[3][j] + bias_j[j];
        hi.x = acc[4][j] + bias_j[j]; hi.y = acc[5][j] + bias_j[j];
        hi.z = acc[6][j] + bias_j[j]; hi.w = acc[7][j] + bias_j[j];
        size_t base = ((size_t)(t0 + tt) * G4H + n0 + tn * 4 + j) * 32 + bb;
        *(float4*)(C + base)     = lo;
        *(float4*)(C + base + 4) = hi;
    }
}

// ---------------------------------------------------------------------------
// Kernel 3: persistent LSTM layer, 512 threads/block, packed f32x2 dot.
// grid = 128 blocks, 4 j per block. Thread = (b=lane, r = w>>2, ks = w&3).
// NEW: fence-free monotonic barrier (red.release arrive / ld.acquire poll)
// and gate prefetch for t+1 overlapped with the barrier wait.
// ---------------------------------------------------------------------------
#define HSP 516   // padded row stride of hs (floats)
#define NBLK 128

__global__ void __launch_bounds__(512)
lstm_layer(const float* __restrict__ xgT, const float* __restrict__ whh,
           float* __restrict__ ht)
{
    extern __shared__ float sm[];
    float* hs  = sm;               // 32 * 516 floats: hs[b][k]
    float* wsm = sm + 32 * HSP;    // 8192 floats: 16 rows x 512, [(r*4+g)*512 + k]
    float* red = wsm + 8192;       // 2048 floats: [(r*4+g)*4 + ks]*32 + b

    const int tid = threadIdx.x;
    const int b   = tid & 31;
    const int w   = tid >> 5;           // 0..15
    const int r   = w >> 2;             // 0..3 (local j)
    const int ks  = w & 3;              // k-quarter (128 k each)
    const int j0  = blockIdx.x * 4;
    const int j   = j0 + r;

    // stage 16 w_hh rows once — coalesced float4
    float4* wsm4 = (float4*)wsm;
    for (int fi = tid; fi < 2048; fi += 512) {
        int lr = fi >> 7, kq = fi & 127;
        int g = lr & 3, rr = lr >> 2;
        int grow = g * Hh + j0 + rr;
        wsm4[lr * 128 + kq] = *(const float4*)(whh + (size_t)grow * Hh + kq * 4);
    }
    __syncthreads();

    const ulonglong2* w0 = (const ulonglong2*)(wsm + (r * 4 + 0) * 512 + ks * 128);
    const ulonglong2* w1 = (const ulonglong2*)(wsm + (r * 4 + 1) * 512 + ks * 128);
    const ulonglong2* w2 = (const ulonglong2*)(wsm + (r * 4 + 2) * 512 + ks * 128);
    const ulonglong2* w3 = (const ulonglong2*)(wsm + (r * 4 + 3) * 512 + ks * 128);
    const ulonglong2* hv = (const ulonglong2*)(hs + b * HSP + ks * 128);

    unsigned* ctrp = &g_bar_ctr;
    float creg = 0.f;

    // prefetch gates for t = 0 (ks==0 warps only)
    float gi = 0.f, gf = 0.f, gg = 0.f, go = 0.f;
    if (ks == 0) {
        const size_t xoff = ((size_t)0 * G4H + j) * 32 + b;
        gi = __ldg(xgT + xoff);
        gf = __ldg(xgT + xoff + 512u * 32u);
        gg = __ldg(xgT + xoff + 1024u * 32u);
        go = __ldg(xgT + xoff + 1536u * 32u);
    }

    for (int t = 0; t < Tt; t++) {
        if (t > 0) {
            // stage h_{t-1} from (T,B,H) into transposed hs[b][k]
            const float4* hp = (const float4*)(ht + (size_t)(t - 1) * (Hh * Bz));
            for (int fi = tid; fi < 4096; fi += 512) {
                int bb = fi >> 7, kq = fi & 127;
                float4 v = __ldcg(hp + bb * 128 + kq);
                *(float4*)(hs + bb * HSP + kq * 4) = v;
            }
            __syncthreads();

            unsigned long long acc0 = 0ull, acc1 = 0ull, acc2 = 0ull, acc3 = 0ull;
#pragma unroll 8
            for (int k4 = 0; k4 < 32; k4++) {
                ulonglong2 hq = hv[k4];
                ulonglong2 q0 = w0[k4];
                ulonglong2 q1 = w1[k4];
                ulonglong2 q2 = w2[k4];
                ulonglong2 q3 = w3[k4];
                FFMA2(acc0, hq.x, q0.x); FFMA2(acc0, hq.y, q0.y);
                FFMA2(acc1, hq.x, q1.x); FFMA2(acc1, hq.y, q1.y);
                FFMA2(acc2, hq.x, q2.x); FFMA2(acc2, hq.y, q2.y);
                FFMA2(acc3, hq.x, q3.x); FFMA2(acc3, hq.y, q3.y);
            }
            float l0, h0, l1, h1, l2, h2, l3, h3;
            asm("mov.b64 {%0, %1}, %2;" : "=f"(l0), "=f"(h0) : "l"(acc0));
            asm("mov.b64 {%0, %1}, %2;" : "=f"(l1), "=f"(h1) : "l"(acc1));
            asm("mov.b64 {%0, %1}, %2;" : "=f"(l2), "=f"(h2) : "l"(acc2));
            asm("mov.b64 {%0, %1}, %2;" : "=f"(l3), "=f"(h3) : "l"(acc3));

            red[((r * 4 + 0) * 4 + ks) * 32 + b] = l0 + h0;
            red[((r * 4 + 1) * 4 + ks) * 32 + b] = l1 + h1;
            red[((r * 4 + 2) * 4 + ks) * 32 + b] = l2 + h2;
            red[((r * 4 + 3) * 4 + ks) * 32 + b] = l3 + h3;
            __syncthreads();

            if (ks == 0) {
#pragma unroll
                for (int q = 0; q < 4; q++) {
                    gi += red[((r * 4 + 0) * 4 + q) * 32 + b];
                    gf += red[((r * 4 + 1) * 4 + q) * 32 + b];
                    gg += red[((r * 4 + 2) * 4 + q) * 32 + b];
                    go += red[((r * 4 + 3) * 4 + q) * 32 + b];
                }
            }
        }

        if (ks == 0) {
            float ii = fsig(gi);
            float ff = fsig(gf);
            float gt = ftanh(gg);
            float oo = fsig(go);
            creg = fmaf(ff, creg, ii * gt);
            float hn = oo * ftanh(creg);
            ht[(size_t)t * (Hh * Bz) + b * Hh + j] = hn;    // (T,B,H)
        }

        if (t + 1 < Tt) {
            // ---- fence-free grid barrier (monotonic counter) ----
            // syncthreads orders this block's ht stores before tid0's
            // release-arrive; the acquire-poll + syncthreads on the other
            // side propagates them to every consumer thread.
            __syncthreads();
            if (tid == 0) {
                asm volatile("red.release.gpu.global.add.u32 [%0], %1;"
                             :: "l"(ctrp), "r"(1u) : "memory");
            }
            // prefetch gates for t+1 while the barrier drains
            if (ks == 0) {
                const size_t xoff = ((size_t)(t + 1) * G4H + j) * 32 + b;
                gi = __ldg(xgT + xoff);
                gf = __ldg(xgT + xoff + 512u * 32u);
                gg = __ldg(xgT + xoff + 1024u * 32u);
                go = __ldg(xgT + xoff + 1536u * 32u);
            }
            if (tid == 0) {
                const unsigned target = (unsigned)(t + 1) * NBLK;
                unsigned v;
                while (true) {
                    asm volatile("ld.acquire.gpu.global.u32 %0, [%1];"
                                 : "=r"(v) : "l"(ctrp) : "memory");
                    if (v >= target) break;
                    __nanosleep(20);
                }
            }
            __syncthreads();
        }
    }
}

// ---------------------------------------------------------------------------
// Kernel 4: mean-pool over T + linear head, reading (T,B,H). grid = 32 (b).
// ---------------------------------------------------------------------------
__global__ void __launch_bounds__(256)
head_pool(const float* __restrict__ h3, const float* __restrict__ hw,
          const float* __restrict__ hb, float* __restrict__ out)
{
    __shared__ float feat[512];
    const int b = blockIdx.x, tid = threadIdx.x;
    for (int j = tid; j < Hh; j += 256) {
        float s = 0.f;
        for (int t = 0; t < Tt; t++)
            s += h3[((size_t)t * Bz + b) * Hh + j];
        feat[j] = s * (1.f / (float)Tt);
    }
    __syncthreads();
    for (int n = tid; n < NCLS; n += 256) {
        float s = __ldg(hb + n);
        for (int jj = 0; jj < Hh; jj++)
            s = fmaf(feat[jj], __ldg(hw + (size_t)n * Hh + jj), s);
        out[b * NCLS + n] = s;
    }
}

// ---------------------------------------------------------------------------
// Host launcher
// ---------------------------------------------------------------------------
extern "C" void kernel_launch(void* const* d_in, const int* in_sizes, int n_in,
                              void* d_out, int out_size)
{
    (void)out_size;
    const float* x     = (const float*)d_in[0];
    const float* convw = (const float*)d_in[1];
    const float* gam   = (const float*)d_in[2];
    const float* bet   = (const float*)d_in[3];
    const float *hw, *hb, *wih[3], *whh[3], *bvec[3];

    if (n_in >= 15 && in_sizes[4] == NCLS * Hh) {
        hw = (const float*)d_in[4];
        hb = (const float*)d_in[5];
        for (int l = 0; l < 3; l++) {
            wih[l]  = (const float*)d_in[6 + 3 * l];
            whh[l]  = (const float*)d_in[7 + 3 * l];
            bvec[l] = (const float*)d_in[8 + 3 * l];
        }
    } else {
        for (int l = 0; l < 3; l++) {
            wih[l]  = (const float*)d_in[4 + 3 * l];
            whh[l]  = (const float*)d_in[5 + 3 * l];
            bvec[l] = (const float*)d_in[6 + 3 * l];
        }
        hw = (const float*)d_in[13];
        hb = (const float*)d_in[14];
    }

    float *feat0, *xgp, *htp;
    cudaGetSymbolAddress((void**)&feat0, g_feat0);
    cudaGetSymbolAddress((void**)&xgp,   g_xg);
    cudaGetSymbolAddress((void**)&htp,   g_ht);

    const int conv_smem  = (16 * 520 + 16 * 9 * 32) * 4;          // 51712 B
    const int layer_smem = (32 * HSP + 8192 + 2048) * 4;          // 107008 B
    cudaFuncSetAttribute(conv_gn_relu, cudaFuncAttributeMaxDynamicSharedMemorySize, conv_smem);
    cudaFuncSetAttribute(lstm_layer,   cudaFuncAttributeMaxDynamicSharedMemorySize, layer_smem);

    conv_gn_relu<<<Bz * GN, 512, conv_smem>>>(x, convw, gam, bet, feat0);

    for (int l = 0; l < 3; l++) {
        const float* Ain = (l == 0) ? feat0 : htp;
        const int Kd = (l == 0) ? NF : Hh;
        gemm_xproj<<<dim3(G4H / 64, Tt / 4), 256>>>(Ain, wih[l], bvec[l], xgp, Kd);
        bar_reset<<<1, 1>>>();
        lstm_layer<<<NBLK, 512, layer_smem>>>(xgp, whh[l], htp);
    }

    head_pool<<<Bz, 256>>>(htp, hw, hb, (float*)d_out);
}